// round 10
// baseline (speedup 1.0000x reference)
#include <cuda_runtime.h>

// Problem shapes (fixed by setup_inputs)
#define BN 64
#define VN 64
#define DN 64
#define HN 64
#define EN 4032     // V*(V-1)
#define ETN 2
#define OUTC (DN + HN)   // 128

// Node-factored first layer: A[b][v][h] = b1[1][h] + sum_d in[b][v][d]*W1[1][h][d]
//                            Bm[b][v][h] =            sum_d in[b][v][d]*W1[1][h][DN+d]
__device__ float g_A [BN * VN * HN];
__device__ float g_Bm[BN * VN * HN];

__device__ __forceinline__ unsigned f2tf32(float x) {
    unsigned r;
    asm("cvt.rna.tf32.f32 %0, %1;" : "=r"(r) : "f"(x));
    return r;
}
// Packed f32x2 add (sm_100+)
union F2U { float2 f; unsigned long long u; };
__device__ __forceinline__ float2 fadd2(float2 a, float2 b) {
    F2U x, y, r; x.f = a; y.f = b;
    asm("add.rn.f32x2 %0, %1, %2;" : "=l"(r.u) : "l"(x.u), "l"(y.u));
    return r.f;
}

// ---------------------------------------------------------------------------
// Kernel 1: node-factored layer-1 precompute (fp32 exact) + output init
// (inputs copy into [0:64], ZEROS into [64:128] for the edge kernel's atomics).
// ---------------------------------------------------------------------------
__global__ __launch_bounds__(256)
void precompute_kernel(const float* __restrict__ inp,
                       const float* __restrict__ W1,
                       const float* __restrict__ b1,
                       float* __restrict__ out) {
    __shared__ __align__(16) float W1r[DN][68];
    __shared__ __align__(16) float W1s[DN][68];

    int b   = blockIdx.x;
    int v0  = blockIdx.y * 32;
    int tid = threadIdx.x;
    const float* inb = inp + b * VN * DN;

    for (int idx = tid; idx < 32 * DN; idx += 256) {
        int v = v0 + (idx >> 6), d = idx & 63;
        float* o = out + ((size_t)(b * VN + v)) * OUTC;
        o[d]      = inb[v * DN + d];
        o[DN + d] = 0.0f;                 // zero agg half for atomic accumulation
    }
    const float* W1e = W1 + HN * 2 * DN;  // edge type 1
    for (int idx = tid; idx < HN * 2 * DN; idx += 256) {
        int h = idx >> 7, d = idx & 127;
        float w = W1e[idx];
        if (d < DN) W1r[d][h] = w;
        else        W1s[d - DN][h] = w;
    }
    __syncthreads();

    int ty = tid >> 4, tx = tid & 15;
    float acc1[2][4], acc2[2][4];
    #pragma unroll
    for (int i = 0; i < 2; i++)
        #pragma unroll
        for (int j = 0; j < 4; j++) { acc1[i][j] = 0.f; acc2[i][j] = 0.f; }

    #pragma unroll 8
    for (int d = 0; d < DN; d++) {
        float xv[2];
        xv[0] = inb[(v0 + ty) * DN + d];
        xv[1] = inb[(v0 + ty + 16) * DN + d];
        float4 wr = *(const float4*)&W1r[d][4 * tx];
        float4 ws = *(const float4*)&W1s[d][4 * tx];
        #pragma unroll
        for (int i = 0; i < 2; i++) {
            acc1[i][0] += xv[i] * wr.x;  acc1[i][1] += xv[i] * wr.y;
            acc1[i][2] += xv[i] * wr.z;  acc1[i][3] += xv[i] * wr.w;
            acc2[i][0] += xv[i] * ws.x;  acc2[i][1] += xv[i] * ws.y;
            acc2[i][2] += xv[i] * ws.z;  acc2[i][3] += xv[i] * ws.w;
        }
    }
    float* Ab = g_A  + b * VN * HN;
    float* Bb = g_Bm + b * VN * HN;
    #pragma unroll
    for (int j = 0; j < 4; j++) {
        int h = 4 * tx + j;
        float bias = b1[HN + h];
        #pragma unroll
        for (int i = 0; i < 2; i++) {
            int v = v0 + ty + 16 * i;
            Ab[v * HN + h] = acc1[i][j] + bias;
            Bb[v * HN + h] = acc2[i][j];
        }
    }
}

// ---------------------------------------------------------------------------
// Kernel 2: barrier-free transposed-GEMM edge MLP.
// B/A fragments built inline from DIRECT LDG.128 of g_Bm/g_A (L1-resident:
// every warp in the block reads the same 16KB Bm tile). No cp.async, no
// smem staging, no mainloop barriers — warps fully decoupled after prologue.
// Physical-k permutation: mma ks=2kq+e uses phys k = kq*16 + ctid*4 + 2e(+1),
// so every B LDG.128 covers 8 rows x 64B contiguous (100% sectors).
// Block = (2 receivers) x (4 batches); 8 warps: rl=w>>2, oh=w&1 (2 m-tiles,
// obase=oh*32), sh=(w>>1)&1 (sender half, 4 n-tiles). Sender halves combine
// via atomicAdd (RED.F32) into the zero-initialized output.
// ---------------------------------------------------------------------------
__global__ __launch_bounds__(256, 2)
void edge_mma_kernel(const float* __restrict__ edges,
                     const float* __restrict__ W2,
                     const float* __restrict__ b2,
                     float* __restrict__ out) {
    __shared__ float Wst[64 * 68];   // W2[1] tf32, [o][k] pitch 68
    __shared__ float wva[4 * 128];   // edge weights, 4 batches

    int bbase = blockIdx.y * 4;
    int rbase = blockIdx.x * 2;
    int tid   = threadIdx.x;
    int w     = tid >> 5;
    int l     = tid & 31;
    int gid   = l >> 2;        // lane row-group
    int ctid  = l & 3;         // lane k-group
    int oh    = w & 1;
    int sh    = (w >> 1) & 1;
    int rl    = w >> 2;
    int obase = oh * 32;

    // --- Stage W2[1]-tf32 (pre-scaled by 1+2^-11 to offset H truncation) ---
    {
        const float* W2e = W2 + HN * HN;
        for (int idx = tid; idx < HN * HN; idx += 256) {
            int o = idx >> 6, kk = idx & 63;
            Wst[o * 68 + kk] =
                __uint_as_float(f2tf32(W2e[idx] * 1.00048828125f));
        }
    }
    // --- Edge weights for 4 batches (closed-form e(s,r) = s*63 + r - (r>s)) ---
    for (int idx = tid; idx < 512; idx += 256) {
        int bi = idx >> 7, row = idx & 127;
        int srl = row >> 6, s = row & 63;
        int r = rbase + srl;
        float wgt = 0.f;
        if (s != r) {
            int e = s * 63 + r - (r > s ? 1 : 0);
            wgt = edges[((size_t)((bbase + bi) * EN + e)) * ETN + 1];
        }
        wva[idx] = wgt;
    }
    __syncthreads();   // the ONLY block-wide barrier

    // --- W2 A-fragments -> registers (2 m-tiles), permuted physical k:
    //     slot(ks=2kq+e, b0) -> k = kq*16 + ctid*4 + 2e ; b1 -> +1 ---
    unsigned a0r[8][4], a1r[8][4];
    float bias[2][2];
    {
        int r0 = obase + gid;
        #pragma unroll
        for (int ks = 0; ks < 8; ks++) {
            int k0 = (ks >> 1) * 16 + ctid * 4 + (ks & 1) * 2;
            a0r[ks][0] = __float_as_uint(Wst[r0 * 68 + k0]);
            a0r[ks][2] = __float_as_uint(Wst[r0 * 68 + k0 + 1]);
            a0r[ks][1] = __float_as_uint(Wst[(r0 + 8) * 68 + k0]);
            a0r[ks][3] = __float_as_uint(Wst[(r0 + 8) * 68 + k0 + 1]);
            a1r[ks][0] = __float_as_uint(Wst[(r0 + 16) * 68 + k0]);
            a1r[ks][2] = __float_as_uint(Wst[(r0 + 16) * 68 + k0 + 1]);
            a1r[ks][1] = __float_as_uint(Wst[(r0 + 24) * 68 + k0]);
            a1r[ks][3] = __float_as_uint(Wst[(r0 + 24) * 68 + k0 + 1]);
        }
        bias[0][0] = b2[HN + obase + gid];
        bias[0][1] = b2[HN + obase + 8 + gid];
        bias[1][0] = b2[HN + obase + 16 + gid];
        bias[1][1] = b2[HN + obase + 24 + gid];
    }

    for (int bi = 0; bi < 4; bi++) {
        int b = bbase + bi;

        // A-row values (receiver), direct LDG.128, L1-hot
        float4 a4[4];
        {
            const float* Ar = g_A + ((size_t)(b * VN + rbase + rl)) * HN + ctid * 4;
            #pragma unroll
            for (int kq = 0; kq < 4; kq++)
                a4[kq] = *(const float4*)&Ar[kq * 16];
        }

        float pa[2][2] = {{0.f, 0.f}, {0.f, 0.f}};
        const float* wvb = wva + bi * 128 + rl * 64;
        #pragma unroll
        for (int j = 0; j < 4; j++) {
            int nt = sh * 4 + j;
            // B rows: senders nt*8+gid; direct LDG.128, dense warp pattern
            const float* Br = g_Bm + ((size_t)(b * VN + nt * 8 + gid)) * HN + ctid * 4;
            float4 b4[4];
            #pragma unroll
            for (int kq = 0; kq < 4; kq++)
                b4[kq] = *(const float4*)&Br[kq * 16];

            float c0[4] = {0.f, 0.f, 0.f, 0.f};
            float c1[4] = {0.f, 0.f, 0.f, 0.f};
            #pragma unroll
            for (int ks = 0; ks < 8; ks++) {
                int kq = ks >> 1;
                float2 bb = (ks & 1) ? make_float2(b4[kq].z, b4[kq].w)
                                     : make_float2(b4[kq].x, b4[kq].y);
                float2 aa = (ks & 1) ? make_float2(a4[kq].z, a4[kq].w)
                                     : make_float2(a4[kq].x, a4[kq].y);
                float2 hv = fadd2(aa, bb);
                unsigned h0 = __float_as_uint(fmaxf(hv.x, 0.f));
                unsigned h1 = __float_as_uint(fmaxf(hv.y, 0.f));
                asm volatile(
                    "mma.sync.aligned.m16n8k8.row.col.f32.tf32.tf32.f32 "
                    "{%0,%1,%2,%3}, {%4,%5,%6,%7}, {%8,%9}, {%0,%1,%2,%3};"
                    : "+f"(c0[0]), "+f"(c0[1]), "+f"(c0[2]), "+f"(c0[3])
                    : "r"(a0r[ks][0]), "r"(a0r[ks][1]),
                      "r"(a0r[ks][2]), "r"(a0r[ks][3]),
                      "r"(h0), "r"(h1));
                asm volatile(
                    "mma.sync.aligned.m16n8k8.row.col.f32.tf32.tf32.f32 "
                    "{%0,%1,%2,%3}, {%4,%5,%6,%7}, {%8,%9}, {%0,%1,%2,%3};"
                    : "+f"(c1[0]), "+f"(c1[1]), "+f"(c1[2]), "+f"(c1[3])
                    : "r"(a1r[ks][0]), "r"(a1r[ks][1]),
                      "r"(a1r[ks][2]), "r"(a1r[ks][3]),
                      "r"(h0), "r"(h1));
            }
            int scol = nt * 8 + 2 * ctid;
            float w0 = wvb[scol], w1 = wvb[scol + 1];
            pa[0][0] += w0 * fmaxf(c0[0] + bias[0][0], 0.f)
                      + w1 * fmaxf(c0[1] + bias[0][0], 0.f);
            pa[0][1] += w0 * fmaxf(c0[2] + bias[0][1], 0.f)
                      + w1 * fmaxf(c0[3] + bias[0][1], 0.f);
            pa[1][0] += w0 * fmaxf(c1[0] + bias[1][0], 0.f)
                      + w1 * fmaxf(c1[1] + bias[1][0], 0.f);
            pa[1][1] += w0 * fmaxf(c1[2] + bias[1][1], 0.f)
                      + w1 * fmaxf(c1[3] + bias[1][1], 0.f);
        }
        // Reduce over the 4 sender-pair lane-groups
        #pragma unroll
        for (int ot = 0; ot < 2; ot++)
            #pragma unroll
            for (int hf = 0; hf < 2; hf++) {
                pa[ot][hf] += __shfl_xor_sync(0xFFFFFFFFu, pa[ot][hf], 1);
                pa[ot][hf] += __shfl_xor_sync(0xFFFFFFFFu, pa[ot][hf], 2);
            }
        // Combine sender halves via RED.F32 into zero-initialized output
        if (ctid == 0) {
            float* dst = out + ((size_t)(b * VN + rbase + rl)) * OUTC + DN + obase;
            atomicAdd(&dst[gid],      pa[0][0]);
            atomicAdd(&dst[gid + 8],  pa[0][1]);
            atomicAdd(&dst[gid + 16], pa[1][0]);
            atomicAdd(&dst[gid + 24], pa[1][1]);
        }
    }
}

// ---------------------------------------------------------------------------
// Launch
// ---------------------------------------------------------------------------
extern "C" void kernel_launch(void* const* d_in, const int* in_sizes, int n_in,
                              void* d_out, int out_size) {
    const float* inputs = (const float*)d_in[0];
    const float* edges  = (const float*)d_in[1];
    const float* W1     = (const float*)d_in[2];
    const float* b1     = (const float*)d_in[3];
    const float* W2     = (const float*)d_in[4];
    const float* b2     = (const float*)d_in[5];
    float* out = (float*)d_out;

    {
        dim3 grid(BN, 2);
        precompute_kernel<<<grid, 256>>>(inputs, W1, b1, out);
    }
    {
        dim3 grid(VN / 2, BN / 4);   // 32 x 16 = 512 blocks
        edge_mma_kernel<<<grid, 256>>>(edges, W2, b2, out);
    }
}

// round 11
// speedup vs baseline: 1.1214x; 1.1214x over previous
#include <cuda_runtime.h>
#include <cuda_fp16.h>

// Problem shapes (fixed by setup_inputs)
#define BN 64
#define VN 64
#define DN 64
#define HN 64
#define EN 4032     // V*(V-1)
#define ETN 2
#define OUTC (DN + HN)   // 128

// Node-factored first layer: A[b][v][h] = b1[1][h] + sum_d in[b][v][d]*W1[1][h][d]
//                            Bm[b][v][h] =            sum_d in[b][v][d]*W1[1][h][DN+d]
__device__ float g_A [BN * VN * HN];
__device__ float g_Bm[BN * VN * HN];

__device__ __forceinline__ void cp16(unsigned dst_smem, const void* src) {
    asm volatile("cp.async.ca.shared.global [%0], [%1], 16;"
                 :: "r"(dst_smem), "l"(src));
}
// Packed f32x2 add (sm_100+)
union F2U { float2 f; unsigned long long u; };
__device__ __forceinline__ float2 fadd2(float2 a, float2 b) {
    F2U x, y, r; x.f = a; y.f = b;
    asm("add.rn.f32x2 %0, %1, %2;" : "=l"(r.u) : "l"(x.u), "l"(y.u));
    return r.f;
}
__device__ __forceinline__ unsigned pack_h2(float lo, float hi) {
    __half2 h = __floats2half2_rn(lo, hi);
    return *reinterpret_cast<unsigned*>(&h);
}
__device__ __forceinline__ unsigned relu_h2(unsigned x) {
    __half2 h = *reinterpret_cast<__half2*>(&x);
    __half2 z = __half2half2(__float2half(0.f));
    h = __hmax2(h, z);
    return *reinterpret_cast<unsigned*>(&h);
}

// ---------------------------------------------------------------------------
// Kernel 1: node-factored layer-1 precompute (fp32 exact) + output init
// (inputs copy into [0:64], ZEROS into [64:128] for edge-kernel atomics).
// ---------------------------------------------------------------------------
__global__ __launch_bounds__(256)
void precompute_kernel(const float* __restrict__ inp,
                       const float* __restrict__ W1,
                       const float* __restrict__ b1,
                       float* __restrict__ out) {
    __shared__ __align__(16) float W1r[DN][68];
    __shared__ __align__(16) float W1s[DN][68];

    int b   = blockIdx.x;
    int v0  = blockIdx.y * 32;
    int tid = threadIdx.x;
    const float* inb = inp + b * VN * DN;

    for (int idx = tid; idx < 32 * DN; idx += 256) {
        int v = v0 + (idx >> 6), d = idx & 63;
        float* o = out + ((size_t)(b * VN + v)) * OUTC;
        o[d]      = inb[v * DN + d];
        o[DN + d] = 0.0f;                 // zero agg half for atomic accumulation
    }
    const float* W1e = W1 + HN * 2 * DN;  // edge type 1
    for (int idx = tid; idx < HN * 2 * DN; idx += 256) {
        int h = idx >> 7, d = idx & 127;
        float w = W1e[idx];
        if (d < DN) W1r[d][h] = w;
        else        W1s[d - DN][h] = w;
    }
    __syncthreads();

    int ty = tid >> 4, tx = tid & 15;
    float acc1[2][4], acc2[2][4];
    #pragma unroll
    for (int i = 0; i < 2; i++)
        #pragma unroll
        for (int j = 0; j < 4; j++) { acc1[i][j] = 0.f; acc2[i][j] = 0.f; }

    #pragma unroll 8
    for (int d = 0; d < DN; d++) {
        float xv[2];
        xv[0] = inb[(v0 + ty) * DN + d];
        xv[1] = inb[(v0 + ty + 16) * DN + d];
        float4 wr = *(const float4*)&W1r[d][4 * tx];
        float4 ws = *(const float4*)&W1s[d][4 * tx];
        #pragma unroll
        for (int i = 0; i < 2; i++) {
            acc1[i][0] += xv[i] * wr.x;  acc1[i][1] += xv[i] * wr.y;
            acc1[i][2] += xv[i] * wr.z;  acc1[i][3] += xv[i] * wr.w;
            acc2[i][0] += xv[i] * ws.x;  acc2[i][1] += xv[i] * ws.y;
            acc2[i][2] += xv[i] * ws.z;  acc2[i][3] += xv[i] * ws.w;
        }
    }
    float* Ab = g_A  + b * VN * HN;
    float* Bb = g_Bm + b * VN * HN;
    #pragma unroll
    for (int j = 0; j < 4; j++) {
        int h = 4 * tx + j;
        float bias = b1[HN + h];
        #pragma unroll
        for (int i = 0; i < 2; i++) {
            int v = v0 + ty + 16 * i;
            Ab[v * HN + h] = acc1[i][j] + bias;
            Bb[v * HN + h] = acc2[i][j];
        }
    }
}

// ---------------------------------------------------------------------------
// Kernel 2: fp16 m16n8k16 transposed-GEMM edge MLP (half chain depth).
// Pipeline structure of R8 (best): cp.async double-buffered Bm/A staging,
// one barrier per batch-iter, inline B-fragment build from smem.
// Physical-k permutation: mma step ms, lane ctid covers phys
//   k = ctid*16 + ms*4 + {0..3}  (one contiguous 64B run per lane).
// Block = (2 receivers) x (4 batches); grid 32 x 16 = 512, 3 blocks/SM.
// 8 warps: rl=w>>2 (receiver), oh=w&1 (2 m16-tiles obase=oh*32),
// sh=(w>>1)&1 (sender half, 4 n-tiles). Sender halves combine via RED.F32.
// ---------------------------------------------------------------------------
__global__ __launch_bounds__(256, 3)
void edge_mma_kernel(const float* __restrict__ edges,
                     const float* __restrict__ W2,
                     const float* __restrict__ b2,
                     float* __restrict__ out) {
    __shared__ __align__(16) float Bs[2 * 4352];   // 2 x [64][68] Bm (swizzled chunks)
    __shared__ __align__(16) float As[2 * 128];    // 2 x [2][64] raw A rows
    __shared__ float wva[4 * 128];                 // edge weights, 4 batches

    int bbase = blockIdx.y * 4;
    int rbase = blockIdx.x * 2;
    int tid   = threadIdx.x;
    int w     = tid >> 5;
    int l     = tid & 31;
    int gid   = l >> 2;        // lane row-group
    int ctid  = l & 3;         // lane k-group
    int oh    = w & 1;
    int sh    = (w >> 1) & 1;
    int rl    = w >> 2;
    int obase = oh * 32;

    unsigned bsA = (unsigned)__cvta_generic_to_shared(Bs);
    unsigned asA = (unsigned)__cvta_generic_to_shared(As);

    // --- Issue cp.async for batch 0 into Bs buf0 (swizzled 16B chunks) ---
    {
        const float* src = g_Bm + (size_t)bbase * VN * HN;
        #pragma unroll
        for (int t = 0; t < 4; t++) {
            int c = tid + t * 256;            // 16B chunk id 0..1023
            int s = c >> 4, q = c & 15;
            int slot = q ^ ((q & 8) >> 2);
            cp16(bsA + (s * 68 + slot * 4) * 4, src + c * 4);
        }
        if (tid < 32)
            cp16(asA + tid * 16,
                 g_A + ((size_t)(bbase * VN + rbase)) * HN + tid * 4);
        asm volatile("cp.async.commit_group;");
    }

    // --- Stage W2[1] (f32) into Bs buf1 (prologue only; freed at bi=0) ---
    {
        const float* W2e = W2 + HN * HN;
        float* Wst = Bs + 4352;
        for (int idx = tid; idx < HN * HN; idx += 256) {
            int o = idx >> 6, kk = idx & 63;
            Wst[o * 68 + kk] = W2e[idx];
        }
    }

    // --- Prefetch 4 batches of edge weights (closed-form e(s,r)) ---
    for (int idx = tid; idx < 512; idx += 256) {
        int bi = idx >> 7, row = idx & 127;
        int srl = row >> 6, s = row & 63;
        int r = rbase + srl;
        float wgt = 0.f;
        if (s != r) {
            int e = s * 63 + r - (r > s ? 1 : 0);
            wgt = edges[((size_t)((bbase + bi) * EN + e)) * ETN + 1];
        }
        wva[idx] = wgt;
    }
    __syncthreads();

    // --- W2 A-fragments (fp16) -> registers, permuted phys k.
    //     m16n8k16 A row-major: a0={r,k2c..}, a1={r+8}, a2={r,k2c+8..}, a3={r+8}.
    //     Logical (ms, 2c+e)   -> phys ctid*16+ms*4+e
    //             (ms, 2c+8+e) -> phys ctid*16+ms*4+2+e
    unsigned a0f[4][4], a1f[4][4];
    float bias[2][2];
    {
        const float* Wst = Bs + 4352;
        int r0 = obase + gid;
        #pragma unroll
        for (int ms = 0; ms < 4; ms++) {
            int p = ctid * 16 + ms * 4;
            const float* w0p = Wst + r0 * 68 + p;
            const float* w8p = Wst + (r0 + 8) * 68 + p;
            a0f[ms][0] = pack_h2(w0p[0], w0p[1]);
            a0f[ms][1] = pack_h2(w8p[0], w8p[1]);
            a0f[ms][2] = pack_h2(w0p[2], w0p[3]);
            a0f[ms][3] = pack_h2(w8p[2], w8p[3]);
            const float* w16p = Wst + (r0 + 16) * 68 + p;
            const float* w24p = Wst + (r0 + 24) * 68 + p;
            a1f[ms][0] = pack_h2(w16p[0], w16p[1]);
            a1f[ms][1] = pack_h2(w24p[0], w24p[1]);
            a1f[ms][2] = pack_h2(w16p[2], w16p[3]);
            a1f[ms][3] = pack_h2(w24p[2], w24p[3]);
        }
        bias[0][0] = b2[HN + obase + gid];
        bias[0][1] = b2[HN + obase + 8 + gid];
        bias[1][0] = b2[HN + obase + 16 + gid];
        bias[1][1] = b2[HN + obase + 24 + gid];
    }

    int kqx = (ctid >= 2) ? 2 : 0;   // chunk-swizzle fixup for this lane

    int buf = 0;
    for (int bi = 0; bi < 4; bi++) {
        asm volatile("cp.async.wait_group 0;");
        __syncthreads();
        // batch bi in buf; all warps done with buf^1 (incl. W2 frags at bi=0)

        if (bi < 3) {
            const float* src = g_Bm + (size_t)(bbase + bi + 1) * VN * HN;
            unsigned dstB = bsA + (buf ^ 1) * 4352 * 4;
            #pragma unroll
            for (int t = 0; t < 4; t++) {
                int c = tid + t * 256;
                int s = c >> 4, q = c & 15;
                int slot = q ^ ((q & 8) >> 2);
                cp16(dstB + (s * 68 + slot * 4) * 4, src + c * 4);
            }
            if (tid < 32)
                cp16(asA + (buf ^ 1) * 512 + tid * 16,
                     g_A + ((size_t)((bbase + bi + 1) * VN + rbase)) * HN + tid * 4);
            asm volatile("cp.async.commit_group;");
        }

        // This lane's 16 A values (contiguous phys k run), broadcast LDS.128
        float4 a4[4];
        {
            const float* Ar = As + buf * 128 + rl * 64 + ctid * 16;
            #pragma unroll
            for (int ms = 0; ms < 4; ms++)
                a4[ms] = *(const float4*)&Ar[ms * 4];
        }

        float pa[2][2] = {{0.f, 0.f}, {0.f, 0.f}};
        const float* wvb = wva + bi * 128 + rl * 64;
        const float* Bbase = Bs + buf * 4352;
        #pragma unroll
        for (int j = 0; j < 4; j++) {
            int nt = sh * 4 + j;
            const float* Br = Bbase + (nt * 8 + gid) * 68 + ctid * 16;
            float4 b4[4];
            #pragma unroll
            for (int ms = 0; ms < 4; ms++)
                b4[ms] = *(const float4*)&Br[(ms ^ kqx) * 4];

            float c0[4] = {0.f, 0.f, 0.f, 0.f};
            float c1[4] = {0.f, 0.f, 0.f, 0.f};
            #pragma unroll
            for (int ms = 0; ms < 4; ms++) {
                float2 h0 = fadd2(make_float2(a4[ms].x, a4[ms].y),
                                  make_float2(b4[ms].x, b4[ms].y));
                float2 h1 = fadd2(make_float2(a4[ms].z, a4[ms].w),
                                  make_float2(b4[ms].z, b4[ms].w));
                unsigned ub0 = relu_h2(pack_h2(h0.x, h0.y));
                unsigned ub1 = relu_h2(pack_h2(h1.x, h1.y));
                asm volatile(
                    "mma.sync.aligned.m16n8k16.row.col.f32.f16.f16.f32 "
                    "{%0,%1,%2,%3}, {%4,%5,%6,%7}, {%8,%9}, {%0,%1,%2,%3};"
                    : "+f"(c0[0]), "+f"(c0[1]), "+f"(c0[2]), "+f"(c0[3])
                    : "r"(a0f[ms][0]), "r"(a0f[ms][1]),
                      "r"(a0f[ms][2]), "r"(a0f[ms][3]),
                      "r"(ub0), "r"(ub1));
                asm volatile(
                    "mma.sync.aligned.m16n8k16.row.col.f32.f16.f16.f32 "
                    "{%0,%1,%2,%3}, {%4,%5,%6,%7}, {%8,%9}, {%0,%1,%2,%3};"
                    : "+f"(c1[0]), "+f"(c1[1]), "+f"(c1[2]), "+f"(c1[3])
                    : "r"(a1f[ms][0]), "r"(a1f[ms][1]),
                      "r"(a1f[ms][2]), "r"(a1f[ms][3]),
                      "r"(ub0), "r"(ub1));
            }
            int scol = nt * 8 + 2 * ctid;
            float w0 = wvb[scol], w1 = wvb[scol + 1];
            pa[0][0] += w0 * fmaxf(c0[0] + bias[0][0], 0.f)
                      + w1 * fmaxf(c0[1] + bias[0][0], 0.f);
            pa[0][1] += w0 * fmaxf(c0[2] + bias[0][1], 0.f)
                      + w1 * fmaxf(c0[3] + bias[0][1], 0.f);
            pa[1][0] += w0 * fmaxf(c1[0] + bias[1][0], 0.f)
                      + w1 * fmaxf(c1[1] + bias[1][0], 0.f);
            pa[1][1] += w0 * fmaxf(c1[2] + bias[1][1], 0.f)
                      + w1 * fmaxf(c1[3] + bias[1][1], 0.f);
        }
        // Reduce over the 4 sender-pair lane-groups
        #pragma unroll
        for (int ot = 0; ot < 2; ot++)
            #pragma unroll
            for (int hf = 0; hf < 2; hf++) {
                pa[ot][hf] += __shfl_xor_sync(0xFFFFFFFFu, pa[ot][hf], 1);
                pa[ot][hf] += __shfl_xor_sync(0xFFFFFFFFu, pa[ot][hf], 2);
            }
        // Combine sender halves via RED.F32 into zero-initialized output
        if (ctid == 0) {
            float* dst = out + ((size_t)((bbase + bi) * VN + rbase + rl)) * OUTC
                       + DN + obase;
            atomicAdd(&dst[gid],      pa[0][0]);
            atomicAdd(&dst[gid + 8],  pa[0][1]);
            atomicAdd(&dst[gid + 16], pa[1][0]);
            atomicAdd(&dst[gid + 24], pa[1][1]);
        }
        buf ^= 1;
    }
}

// ---------------------------------------------------------------------------
// Launch
// ---------------------------------------------------------------------------
extern "C" void kernel_launch(void* const* d_in, const int* in_sizes, int n_in,
                              void* d_out, int out_size) {
    const float* inputs = (const float*)d_in[0];
    const float* edges  = (const float*)d_in[1];
    const float* W1     = (const float*)d_in[2];
    const float* b1     = (const float*)d_in[3];
    const float* W2     = (const float*)d_in[4];
    const float* b2     = (const float*)d_in[5];
    float* out = (float*)d_out;

    {
        dim3 grid(BN, 2);
        precompute_kernel<<<grid, 256>>>(inputs, W1, b1, out);
    }
    {
        dim3 grid(VN / 2, BN / 4);   // 32 x 16 = 512 blocks, 3/SM target
        edge_mma_kernel<<<grid, 256>>>(edges, W2, b2, out);
    }
}

// round 12
// speedup vs baseline: 1.3207x; 1.1777x over previous
#include <cuda_runtime.h>
#include <cuda_fp16.h>

// Problem shapes (fixed by setup_inputs)
#define BN 64
#define VN 64
#define DN 64
#define HN 64
#define EN 4032     // V*(V-1)
#define ETN 2
#define OUTC (DN + HN)   // 128

// Node-factored first layer, stored FP16:
//   g_Ah[b][v][h] = fp16( b1[1][h] + sum_d in[b][v][d]*W1[1][h][d] )
//   g_Bh[b][v][h] = fp16(            sum_d in[b][v][d]*W1[1][h][DN+d] )
__device__ __half g_Ah[BN * VN * HN];
__device__ __half g_Bh[BN * VN * HN];

__device__ __forceinline__ void cp16(unsigned dst_smem, const void* src) {
    asm volatile("cp.async.ca.shared.global [%0], [%1], 16;"
                 :: "r"(dst_smem), "l"(src));
}
__device__ __forceinline__ unsigned hadd2u(unsigned a, unsigned b) {
    __half2 r = __hadd2(*reinterpret_cast<__half2*>(&a),
                        *reinterpret_cast<__half2*>(&b));
    return *reinterpret_cast<unsigned*>(&r);
}
__device__ __forceinline__ unsigned relu2u(unsigned a) {
    __half2 z = __half2half2(__ushort_as_half(0));
    __half2 r = __hmax2(*reinterpret_cast<__half2*>(&a), z);
    return *reinterpret_cast<unsigned*>(&r);
}

// ---------------------------------------------------------------------------
// Kernel 1: node-factored layer-1 precompute (fp32 math, fp16 store) +
// output init (inputs copy into [0:64], zeros into [64:128] for atomics).
// grid (BN, 4): block = 16 nodes; 256 threads, 1x4 micro-tile.
// ---------------------------------------------------------------------------
__global__ __launch_bounds__(256)
void precompute_kernel(const float* __restrict__ inp,
                       const float* __restrict__ W1,
                       const float* __restrict__ b1,
                       float* __restrict__ out) {
    __shared__ __align__(16) float W1r[DN][68];
    __shared__ __align__(16) float W1s[DN][68];

    int b   = blockIdx.x;
    int v0  = blockIdx.y * 16;
    int tid = threadIdx.x;
    const float* inb = inp + b * VN * DN;

    for (int idx = tid; idx < 16 * DN; idx += 256) {
        int v = v0 + (idx >> 6), d = idx & 63;
        float* o = out + ((size_t)(b * VN + v)) * OUTC;
        o[d]      = inb[v * DN + d];
        o[DN + d] = 0.0f;                 // zero agg half for atomic accumulation
    }
    const float* W1e = W1 + HN * 2 * DN;  // edge type 1
    for (int idx = tid; idx < HN * 2 * DN; idx += 256) {
        int h = idx >> 7, d = idx & 127;
        float w = W1e[idx];
        if (d < DN) W1r[d][h] = w;
        else        W1s[d - DN][h] = w;
    }
    __syncthreads();

    int ty = tid >> 4;          // node v0+ty (16 nodes)
    int tx = tid & 15;          // h cols 4*tx..4*tx+3
    int v  = v0 + ty;

    float acc1[4] = {0.f, 0.f, 0.f, 0.f};
    float acc2[4] = {0.f, 0.f, 0.f, 0.f};

    #pragma unroll 8
    for (int d = 0; d < DN; d++) {
        float xv = inb[v * DN + d];
        float4 wr = *(const float4*)&W1r[d][4 * tx];
        float4 ws = *(const float4*)&W1s[d][4 * tx];
        acc1[0] += xv * wr.x;  acc1[1] += xv * wr.y;
        acc1[2] += xv * wr.z;  acc1[3] += xv * wr.w;
        acc2[0] += xv * ws.x;  acc2[1] += xv * ws.y;
        acc2[2] += xv * ws.z;  acc2[3] += xv * ws.w;
    }

    // Pack 4 halfs -> one 8B store per table
    __half2 pa0 = __floats2half2_rn(acc1[0] + b1[HN + 4 * tx],
                                    acc1[1] + b1[HN + 4 * tx + 1]);
    __half2 pa1 = __floats2half2_rn(acc1[2] + b1[HN + 4 * tx + 2],
                                    acc1[3] + b1[HN + 4 * tx + 3]);
    __half2 pb0 = __floats2half2_rn(acc2[0], acc2[1]);
    __half2 pb1 = __floats2half2_rn(acc2[2], acc2[3]);
    size_t base = (size_t)(b * VN + v) * HN + 4 * tx;
    uint2 ua, ub;
    ua.x = *reinterpret_cast<unsigned*>(&pa0);
    ua.y = *reinterpret_cast<unsigned*>(&pa1);
    ub.x = *reinterpret_cast<unsigned*>(&pb0);
    ub.y = *reinterpret_cast<unsigned*>(&pb1);
    *reinterpret_cast<uint2*>(&g_Ah[base]) = ua;
    *reinterpret_cast<uint2*>(&g_Bh[base]) = ub;
}

// ---------------------------------------------------------------------------
// Kernel 2: all-fp16 m16n8k16 transposed-GEMM edge MLP.
// Node tables stored fp16 -> H build is pure half2: per n-tile
//   2x LDS.128 + 8 hadd2 + 8 hmax2 (no cvt, half the LDS of R11).
// Bm rows chunk-swizzled (slot = c ^ (s&7), rows 128B) -> conflict-free
// quarter-warp LDS.128. W2 staged fp16 into Bm buf1 (8KB), frags extracted
// before mainloop. Block = (2 receivers) x (4 batches); grid 32x16 = 512.
// 8 warps: rl=w>>2, oh=w&1 (2 m16-tiles), sh=(w>>1)&1 (sender half).
// Sender halves combine via RED.F32 into the zero-initialized output.
// ---------------------------------------------------------------------------
__global__ __launch_bounds__(256, 3)
void edge_mma_kernel(const float* __restrict__ edges,
                     const float* __restrict__ W2,
                     const float* __restrict__ b2,
                     float* __restrict__ out) {
    __shared__ __align__(16) __half Bh[2][4096];   // 2 x [64 rows][64 halfs], swizzled
    __shared__ __align__(16) __half Ah[2][128];    // 2 x [2 recv][64 halfs]
    __shared__ float wva[4 * 128];                 // edge weights, 4 batches

    int bbase = blockIdx.y * 4;
    int rbase = blockIdx.x * 2;
    int tid   = threadIdx.x;
    int w     = tid >> 5;
    int l     = tid & 31;
    int gid   = l >> 2;        // lane row-group
    int ctid  = l & 3;         // lane k-group
    int oh    = w & 1;
    int sh    = (w >> 1) & 1;
    int rl    = w >> 2;
    int obase = oh * 32;

    unsigned bhA = (unsigned)__cvta_generic_to_shared(&Bh[0][0]);
    unsigned ahA = (unsigned)__cvta_generic_to_shared(&Ah[0][0]);

    // --- cp.async batch 0 -> Bh[0] (16B chunks, slot = c ^ (s&7)) ---
    {
        const __half* src = g_Bh + (size_t)bbase * VN * HN;
        #pragma unroll
        for (int t = 0; t < 2; t++) {
            int c = tid + t * 256;            // chunk id 0..511
            int s = c >> 3, q = c & 7;
            int slot = q ^ (s & 7);
            cp16(bhA + s * 128 + slot * 16, src + c * 8);
        }
        if (tid < 16)
            cp16(ahA + tid * 16,
                 g_Ah + ((size_t)(bbase * VN + rbase)) * HN + tid * 8);
        asm volatile("cp.async.commit_group;");
    }

    // --- Stage W2[1] as fp16 into Bh[1] (linear [o][k], 8KB) ---
    {
        const float* W2e = W2 + HN * HN;
        __half* Wh = Bh[1];
        for (int idx = tid; idx < HN * HN; idx += 256)
            Wh[idx] = __float2half_rn(W2e[idx]);
    }

    // --- 4 batches of edge weights (closed-form e(s,r) = s*63 + r - (r>s)) ---
    for (int idx = tid; idx < 512; idx += 256) {
        int bi = idx >> 7, row = idx & 127;
        int srl = row >> 6, s = row & 63;
        int r = rbase + srl;
        float wgt = 0.f;
        if (s != r) {
            int e = s * 63 + r - (r > s ? 1 : 0);
            wgt = edges[((size_t)((bbase + bi) * EN + e)) * ETN + 1];
        }
        wva[idx] = wgt;
    }
    __syncthreads();

    // --- W2 A-fragments (fp16) from Bh[1]; permuted phys k = ctid*16+ms*4+{0..3}
    //     a0={r,log 2c+e}, a1={r+8}, a2={r,log 2c+8+e}, a3={r+8} ---
    unsigned a0f[4][4], a1f[4][4];
    float bias[2][2];
    {
        const __half* Wh = Bh[1];
        int r0 = obase + gid;
        #pragma unroll
        for (int ms = 0; ms < 4; ms++) {
            int p = ctid * 16 + ms * 4;
            a0f[ms][0] = *(const unsigned*)&Wh[r0 * 64 + p];
            a0f[ms][2] = *(const unsigned*)&Wh[r0 * 64 + p + 2];
            a0f[ms][1] = *(const unsigned*)&Wh[(r0 + 8) * 64 + p];
            a0f[ms][3] = *(const unsigned*)&Wh[(r0 + 8) * 64 + p + 2];
            a1f[ms][0] = *(const unsigned*)&Wh[(r0 + 16) * 64 + p];
            a1f[ms][2] = *(const unsigned*)&Wh[(r0 + 16) * 64 + p + 2];
            a1f[ms][1] = *(const unsigned*)&Wh[(r0 + 24) * 64 + p];
            a1f[ms][3] = *(const unsigned*)&Wh[(r0 + 24) * 64 + p + 2];
        }
        bias[0][0] = b2[HN + obase + gid];
        bias[0][1] = b2[HN + obase + 8 + gid];
        bias[1][0] = b2[HN + obase + 16 + gid];
        bias[1][1] = b2[HN + obase + 24 + gid];
    }

    int buf = 0;
    for (int bi = 0; bi < 4; bi++) {
        asm volatile("cp.async.wait_group 0;");
        __syncthreads();
        // batch bi in Bh[buf]/Ah[buf]; everyone done with buf^1
        // (at bi==0 that includes the W2 fragment extraction above).

        if (bi < 3) {
            const __half* src = g_Bh + (size_t)(bbase + bi + 1) * VN * HN;
            unsigned dstB = bhA + (buf ^ 1) * 8192;
            #pragma unroll
            for (int t = 0; t < 2; t++) {
                int c = tid + t * 256;
                int s = c >> 3, q = c & 7;
                int slot = q ^ (s & 7);
                cp16(dstB + s * 128 + slot * 16, src + c * 8);
            }
            if (tid < 16)
                cp16(ahA + (buf ^ 1) * 256 + tid * 16,
                     g_Ah + ((size_t)((bbase + bi + 1) * VN + rbase)) * HN + tid * 8);
            asm volatile("cp.async.commit_group;");
        }

        // A cache: 16 halfs (phys k run) = 2x LDS.128 broadcast
        unsigned aa[8];
        {
            const __half* Ar = Ah[buf] + rl * 64 + ctid * 16;
            uint4 la0 = *(const uint4*)&Ar[0];
            uint4 la1 = *(const uint4*)&Ar[8];
            aa[0] = la0.x; aa[1] = la0.y; aa[2] = la0.z; aa[3] = la0.w;
            aa[4] = la1.x; aa[5] = la1.y; aa[6] = la1.z; aa[7] = la1.w;
        }

        float pa[2][2] = {{0.f, 0.f}, {0.f, 0.f}};
        const float* wvb = wva + bi * 128 + rl * 64;
        #pragma unroll
        for (int j = 0; j < 4; j++) {
            int nt = sh * 4 + j;
            int s  = nt * 8 + gid;
            const __half* srow = Bh[buf] + s * 64;
            int c0 = (2 * ctid)     ^ (s & 7);
            int c1 = (2 * ctid + 1) ^ (s & 7);
            uint4 lb0 = *(const uint4*)&srow[c0 * 8];   // phys k ctid*16+0..7  (ms 0,1)
            uint4 lb1 = *(const uint4*)&srow[c1 * 8];   // phys k ctid*16+8..15 (ms 2,3)
            unsigned bb[8] = {lb0.x, lb0.y, lb0.z, lb0.w,
                              lb1.x, lb1.y, lb1.z, lb1.w};

            float c0a[4] = {0.f, 0.f, 0.f, 0.f};
            float c1a[4] = {0.f, 0.f, 0.f, 0.f};
            #pragma unroll
            for (int ms = 0; ms < 4; ms++) {
                unsigned ub0 = relu2u(hadd2u(aa[2 * ms],     bb[2 * ms]));
                unsigned ub1 = relu2u(hadd2u(aa[2 * ms + 1], bb[2 * ms + 1]));
                asm volatile(
                    "mma.sync.aligned.m16n8k16.row.col.f32.f16.f16.f32 "
                    "{%0,%1,%2,%3}, {%4,%5,%6,%7}, {%8,%9}, {%0,%1,%2,%3};"
                    : "+f"(c0a[0]), "+f"(c0a[1]), "+f"(c0a[2]), "+f"(c0a[3])
                    : "r"(a0f[ms][0]), "r"(a0f[ms][1]),
                      "r"(a0f[ms][2]), "r"(a0f[ms][3]),
                      "r"(ub0), "r"(ub1));
                asm volatile(
                    "mma.sync.aligned.m16n8k16.row.col.f32.f16.f16.f32 "
                    "{%0,%1,%2,%3}, {%4,%5,%6,%7}, {%8,%9}, {%0,%1,%2,%3};"
                    : "+f"(c1a[0]), "+f"(c1a[1]), "+f"(c1a[2]), "+f"(c1a[3])
                    : "r"(a1f[ms][0]), "r"(a1f[ms][1]),
                      "r"(a1f[ms][2]), "r"(a1f[ms][3]),
                      "r"(ub0), "r"(ub1));
            }
            int scol = nt * 8 + 2 * ctid;
            float w0 = wvb[scol], w1 = wvb[scol + 1];
            pa[0][0] += w0 * fmaxf(c0a[0] + bias[0][0], 0.f)
                      + w1 * fmaxf(c0a[1] + bias[0][0], 0.f);
            pa[0][1] += w0 * fmaxf(c0a[2] + bias[0][1], 0.f)
                      + w1 * fmaxf(c0a[3] + bias[0][1], 0.f);
            pa[1][0] += w0 * fmaxf(c1a[0] + bias[1][0], 0.f)
                      + w1 * fmaxf(c1a[1] + bias[1][0], 0.f);
            pa[1][1] += w0 * fmaxf(c1a[2] + bias[1][1], 0.f)
                      + w1 * fmaxf(c1a[3] + bias[1][1], 0.f);
        }
        // Reduce over the 4 sender-pair lane-groups
        #pragma unroll
        for (int ot = 0; ot < 2; ot++)
            #pragma unroll
            for (int hf = 0; hf < 2; hf++) {
                pa[ot][hf] += __shfl_xor_sync(0xFFFFFFFFu, pa[ot][hf], 1);
                pa[ot][hf] += __shfl_xor_sync(0xFFFFFFFFu, pa[ot][hf], 2);
            }
        // Combine sender halves via RED.F32 into zero-initialized output
        if (ctid == 0) {
            float* dst = out + ((size_t)((bbase + bi) * VN + rbase + rl)) * OUTC
                       + DN + obase;
            atomicAdd(&dst[gid],      pa[0][0]);
            atomicAdd(&dst[gid + 8],  pa[0][1]);
            atomicAdd(&dst[gid + 16], pa[1][0]);
            atomicAdd(&dst[gid + 24], pa[1][1]);
        }
        buf ^= 1;
    }
}

// ---------------------------------------------------------------------------
// Launch
// ---------------------------------------------------------------------------
extern "C" void kernel_launch(void* const* d_in, const int* in_sizes, int n_in,
                              void* d_out, int out_size) {
    const float* inputs = (const float*)d_in[0];
    const float* edges  = (const float*)d_in[1];
    const float* W1     = (const float*)d_in[2];
    const float* b1     = (const float*)d_in[3];
    const float* W2     = (const float*)d_in[4];
    const float* b2     = (const float*)d_in[5];
    float* out = (float*)d_out;

    {
        dim3 grid(BN, 4);    // 256 blocks, 16 nodes each
        precompute_kernel<<<grid, 256>>>(inputs, W1, b1, out);
    }
    {
        dim3 grid(VN / 2, BN / 4);   // 32 x 16 = 512 blocks, 3/SM
        edge_mma_kernel<<<grid, 256>>>(edges, W2, b2, out);
    }
}